// round 4
// baseline (speedup 1.0000x reference)
#include <cuda_runtime.h>
#include <cstdint>

// i1e(x) = exp(-|x|) * I1(x), A&S 9.8.3/9.8.4, same coefficients as the JAX
// reference. Math vectorized 2-wide via Blackwell packed f32x2 FMA/MUL
// (only reachable through inline PTX; ptxas never auto-fuses). MUFU ops
// (EX2/RCP/RSQ) stay scalar — separate pipe, not the issue bottleneck.

typedef unsigned long long u64;

__device__ __forceinline__ u64 pk2(float lo, float hi) {
    u64 r; asm("mov.b64 %0, {%1, %2};" : "=l"(r) : "f"(lo), "f"(hi)); return r;
}
__device__ __forceinline__ void upk2(u64 v, float& lo, float& hi) {
    asm("mov.b64 {%0, %1}, %2;" : "=f"(lo), "=f"(hi) : "l"(v));
}
__device__ __forceinline__ u64 splat2(float v) { return pk2(v, v); }
__device__ __forceinline__ u64 fma2(u64 a, u64 b, u64 c) {
    u64 d; asm("fma.rn.f32x2 %0, %1, %2, %3;" : "=l"(d) : "l"(a), "l"(b), "l"(c)); return d;
}
__device__ __forceinline__ u64 mul2(u64 a, u64 b) {
    u64 d; asm("mul.rn.f32x2 %0, %1, %2;" : "=l"(d) : "l"(a), "l"(b)); return d;
}

// Process two elements through the packed pipes.
__device__ __forceinline__ void i1e_pair(float xa, float xb, float& ra, float& rb) {
    const float axa = fabsf(xa), axb = fabsf(xb);
    const u64 ax2 = pk2(axa, axb);

    // ---- small branch: ax <= 3.75 ----  t = (ax/3.75)^2
    u64 t = mul2(ax2, splat2(1.0f / 3.75f));
    t = mul2(t, t);
    u64 p = splat2(0.00032411f);
    p = fma2(p, t, splat2(0.00301532f));
    p = fma2(p, t, splat2(0.02658733f));
    p = fma2(p, t, splat2(0.15084934f));
    p = fma2(p, t, splat2(0.51498869f));
    p = fma2(p, t, splat2(0.87890594f));
    p = fma2(p, t, splat2(0.5f));
    const float ea = __expf(-axa), eb = __expf(-axb);
    const u64 s2 = mul2(mul2(ax2, p), pk2(ea, eb));

    // ---- large branch: ax > 3.75 ----  tl = 3.75/ax
    // (no clamp: if ax <= 3.75 this lane's large result is discarded below;
    //  inputs here are >= 0.5 so no overflow in the rcp.)
    const u64 tl = pk2(__fdividef(3.75f, axa), __fdividef(3.75f, axb));
    u64 q = splat2(-0.00420059f);
    q = fma2(q, tl, splat2(0.01787654f));
    q = fma2(q, tl, splat2(-0.02895312f));
    q = fma2(q, tl, splat2(0.02282967f));
    q = fma2(q, tl, splat2(-0.01031555f));
    q = fma2(q, tl, splat2(0.00163801f));
    q = fma2(q, tl, splat2(-0.00362018f));
    q = fma2(q, tl, splat2(-0.03988024f));
    q = fma2(q, tl, splat2(0.39894228f));
    const u64 l2 = mul2(q, pk2(rsqrtf(axa), rsqrtf(axb)));

    float sa, sb, la, lb;
    upk2(s2, sa, sb);
    upk2(l2, la, lb);
    const float va = (axa <= 3.75f) ? sa : la;
    const float vb = (axb <= 3.75f) ? sb : lb;
    ra = copysignf(va, xa);   // I1 is odd; inputs never exactly 0 here
    rb = copysignf(vb, xb);
}

__device__ __forceinline__ float4 i1e_vec4(float4 v) {
    float4 r;
    i1e_pair(v.x, v.y, r.x, r.y);
    i1e_pair(v.z, v.w, r.z, r.w);
    return r;
}

// 2 float4 per thread = 8 elements; two independent LDG.128 issued up front.
__global__ void __launch_bounds__(256) ive_kernel_p8(const float4* __restrict__ in,
                                                     float4* __restrict__ out,
                                                     int n4) {
    int i0 = (blockIdx.x * blockDim.x + threadIdx.x) * 2;
    int i1 = i0 + 1;
    if (i1 < n4) {
        float4 a = in[i0];
        float4 b = in[i1];
        out[i0] = i1e_vec4(a);
        out[i1] = i1e_vec4(b);
    } else if (i0 < n4) {
        out[i0] = i1e_vec4(in[i0]);
    }
}

__device__ __forceinline__ float i1e_scalar(float x) {
    float r, dummy;
    i1e_pair(x, x, r, dummy);
    return r;
}

__global__ void ive_kernel_tail(const float* __restrict__ in,
                                float* __restrict__ out,
                                int start, int n) {
    int i = start + blockIdx.x * blockDim.x + threadIdx.x;
    if (i < n) out[i] = i1e_scalar(in[i]);
}

extern "C" void kernel_launch(void* const* d_in, const int* in_sizes, int n_in,
                              void* d_out, int out_size) {
    const float* z = (const float*)d_in[0];
    float* out = (float*)d_out;
    const int n = in_sizes[0];

    const int n4 = n / 4;
    if (n4 > 0) {
        const int threads = 256;
        const int f4_per_block = threads * 2;
        const int blocks = (n4 + f4_per_block - 1) / f4_per_block;
        ive_kernel_p8<<<blocks, threads>>>((const float4*)z, (float4*)out, n4);
    }
    const int rem = n - n4 * 4;
    if (rem > 0) {
        ive_kernel_tail<<<1, 256>>>(z, out, n4 * 4, n);
    }
}